// round 16
// baseline (speedup 1.0000x reference)
#include <cuda_runtime.h>
#include <cuda_fp16.h>
#include <math.h>
#include <stdint.h>

// ---------------- problem constants ----------------
#define TWO_B 512
#define BHALF 256
#define DDIM  512
#define NCLS  100000
#define SCALE 30.0f
#define S_LOG2E 43.280851226668914f  // 30 * log2(e)
#define COS_M 0.8775825618903728f
#define SIN_M 0.4794255386042030f
#define TH   (-0.8775825618903728f)
#define MMRG  0.2397127693021015f

// ---------------- GEMM tiling ----------------
#define MT      128                   // rows per CTA
#define NT      128                   // classes per CTA
#define NTILES  782                   // ceil(NCLS/NT)
#define NPART   784
#define KC      64                    // K fp16 elems per chunk (128 B/row)
#define NCHUNK  8
#define NSTAGE  3
#define ROWB    144                   // padded bytes per smem row (conflict-free)
#define NCONV   64                    // persistent converter CTAs

// smem layout (bytes)
#define A_OFF   0
#define A_STG   (MT * ROWB)                    // 18432, 3 stages
#define B_OFF   (NSTAGE * A_STG)               // 55296
#define B_STG   (NT * ROWB)                    // 18432
#define SR_OFF  (B_OFF + NSTAGE * B_STG)       // 110592 : sRowP[4][128] floats
#define SMEM_BYTES (SR_OFF + 4 * MT * 4)       // 112640 -> 2 CTAs/SM

// ---------------- device scratch ----------------
__device__ __align__(16) uint16_t g_embn[TWO_B * DDIM];      // normalized emb, fp16
__device__ __align__(16) uint16_t g_wn[(size_t)NCLS * DDIM]; // normalized weight, fp16
__device__ int   g_flag[NTILES];                             // tile-converted flags
__device__ float g_part[TWO_B * NPART];
__device__ float g_coslab[TWO_B];
__device__ float g_nll[TWO_B];
__device__ int   g_ticket;                                   // last-block election

// ---------------- helpers ----------------
__device__ __forceinline__ uint32_t smem_u32(const void* p) {
    uint32_t a;
    asm("{ .reg .u64 t; cvta.to.shared.u64 t, %1; cvt.u32.u64 %0, t; }" : "=r"(a) : "l"(p));
    return a;
}
__device__ __forceinline__ void cp16(uint32_t dst, const void* src) {
    asm volatile("cp.async.cg.shared.global [%0], [%1], 16;" :: "r"(dst), "l"(src));
}
__device__ __forceinline__ void cp_commit() { asm volatile("cp.async.commit_group;"); }
__device__ __forceinline__ void cp_wait1()  { asm volatile("cp.async.wait_group 1;"); }

__device__ __forceinline__ uint32_t pack_f16x2(float lo, float hi) {
    uint32_t r;
    asm("cvt.rn.f16x2.f32 %0, %1, %2;" : "=r"(r) : "f"(hi), "f"(lo));
    return r;
}
__device__ __forceinline__ void ldm_x4(uint32_t* r, uint32_t addr) {
    asm volatile("ldmatrix.sync.aligned.m8n8.x4.shared.b16 {%0,%1,%2,%3}, [%4];"
                 : "=r"(r[0]), "=r"(r[1]), "=r"(r[2]), "=r"(r[3]) : "r"(addr));
}
__device__ __forceinline__ void mma_f16(uint32_t* d, const uint32_t* a, const uint32_t* b) {
    asm volatile(
        "mma.sync.aligned.m16n8k16.row.col.f16.f16.f16.f16 "
        "{%0,%1}, {%2,%3,%4,%5}, {%6,%7}, {%0,%1};"
        : "+r"(d[0]), "+r"(d[1])
        : "r"(a[0]), "r"(a[1]), "r"(a[2]), "r"(a[3]), "r"(b[0]), "r"(b[1]));
}
__device__ __forceinline__ int ld_acq(const int* p) {
    int v;
    asm volatile("ld.acquire.gpu.s32 %0, [%1];" : "=r"(v) : "l"(p) : "memory");
    return v;
}

// convert 32 weight rows (8 threads/row, 256 threads) -> normalized fp16
__device__ __forceinline__ void convert_rows(const float* __restrict__ weight,
                                             int base_row, int tid) {
    const int row = base_row + (tid >> 3);
    const int tpr = tid & 7;
    if (row < NCLS) {
        const float4* src = (const float4*)(weight + (size_t)row * DDIM) + tpr * 16;
        float ss = 0.f;
        #pragma unroll
        for (int t = 0; t < 16; t++) {
            float4 v = src[t];
            ss = fmaf(v.x, v.x, fmaf(v.y, v.y, fmaf(v.z, v.z, fmaf(v.w, v.w, ss))));
        }
        ss += __shfl_xor_sync(0xffffffffu, ss, 1);
        ss += __shfl_xor_sync(0xffffffffu, ss, 2);
        ss += __shfl_xor_sync(0xffffffffu, ss, 4);
        const float rinv = rsqrtf(ss);
        uint4* dst = (uint4*)(g_wn + (size_t)row * DDIM) + tpr * 8;
        #pragma unroll
        for (int sub = 0; sub < 4; sub++) {
            float4 v0 = src[sub * 4 + 0];
            float4 v1 = src[sub * 4 + 1];
            float4 v2 = src[sub * 4 + 2];
            float4 v3 = src[sub * 4 + 3];
            uint4 o;
            o.x = pack_f16x2(v0.x * rinv, v0.y * rinv) | 0u;
            o.x = pack_f16x2(v0.x * rinv, v0.y * rinv);
            o.y = pack_f16x2(v0.z * rinv, v0.w * rinv);
            o.z = pack_f16x2(v1.x * rinv, v1.y * rinv);
            o.w = pack_f16x2(v1.z * rinv, v1.w * rinv);
            uint4 p;
            p.x = pack_f16x2(v2.x * rinv, v2.y * rinv);
            p.y = pack_f16x2(v2.z * rinv, v2.w * rinv);
            p.z = pack_f16x2(v3.x * rinv, v3.y * rinv);
            p.w = pack_f16x2(v3.z * rinv, v3.w * rinv);
            dst[sub * 2 + 0] = o;
            dst[sub * 2 + 1] = p;
        }
    }
}

// ============================================================
// Kernel A: normalize embeddings -> fp16 ; reset flags/ticket
// ============================================================
__global__ void k_norm_emb(const float* __restrict__ img,
                           const float* __restrict__ prof) {
    if (blockIdx.x == 0 && threadIdx.x == 0) g_ticket = 0;
    if (blockIdx.x < 391 && threadIdx.x < 2) {
        int f = blockIdx.x * 2 + threadIdx.x;
        if (f < NTILES) g_flag[f] = 0;
    }
    int n = blockIdx.x;
    const float* src = (n < BHALF) ? (img + (size_t)n * DDIM)
                                   : (prof + (size_t)(n - BHALF) * DDIM);
    __shared__ float wsum[8];
    __shared__ float srinv;
    float ss = 0.f;
    for (int d = threadIdx.x; d < DDIM; d += blockDim.x) {
        float v = src[d];
        ss += v * v;
    }
    #pragma unroll
    for (int o = 16; o; o >>= 1) ss += __shfl_xor_sync(0xffffffffu, ss, o);
    if ((threadIdx.x & 31) == 0) wsum[threadIdx.x >> 5] = ss;
    __syncthreads();
    if (threadIdx.x == 0) {
        float t = 0.f;
        #pragma unroll
        for (int w = 0; w < 8; w++) t += wsum[w];
        srinv = rsqrtf(t);
    }
    __syncthreads();
    float rinv = srinv;
    for (int p = threadIdx.x; p < DDIM / 2; p += blockDim.x) {
        float a = src[p * 2] * rinv, b = src[p * 2 + 1] * rinv;
        ((uint32_t*)g_embn)[(size_t)n * (DDIM / 2) + p] = pack_f16x2(a, b);
    }
}

// ============================================================
// Kernel W: persistent converter (64 CTAs), runs on side stream
//   concurrent with k_main; per-tile flag handshake.
// ============================================================
__global__ void __launch_bounds__(256)
k_wprep(const float* __restrict__ weight) {
    const int tid = threadIdx.x;
    for (int y = blockIdx.x; y < NTILES; y += NCONV) {
        #pragma unroll 1
        for (int sub = 0; sub < 4; sub++)
            convert_rows(weight, y * NT + sub * 32, tid);
        __threadfence();
        __syncthreads();
        if (tid == 0) atomicExch(&g_flag[y], 1);
    }
}

// ============================================================
// Kernel B: fp16 mma.sync GEMM (fp16 accum) + exp epilogue
//   Waits on per-tile flag; race-benign self-convert fallback.
// ============================================================
__global__ void __launch_bounds__(512, 2)
k_main(const float* __restrict__ weight, const long long* __restrict__ label) {
    extern __shared__ char smem[];
    const uint32_t sb = smem_u32(smem);
    const int tid   = threadIdx.x;
    const int lane  = tid & 31;
    const int wrp   = tid >> 5;
    const int warpM = wrp & 3;
    const int warpN = wrp >> 2;
    const int g     = lane >> 2;
    const int tig   = lane & 3;

    const int m0   = blockIdx.x * MT;
    const int tile = blockIdx.y;
    const int col0 = tile * NT;

    // wait for converter (bounded; fallback writes identical bytes)
    __shared__ int s_ok;
    if (tid == 0) {
        int it = 0, v;
        while ((v = ld_acq(&g_flag[tile])) == 0 && ++it < 2000) __nanosleep(64);
        s_ok = v;
    }
    __syncthreads();
    if (s_ok == 0) {
        #pragma unroll 1
        for (int sub = 0; sub < 4; sub++)
            if (tid < 256) convert_rows(weight, col0 + sub * 32, tid);
        __threadfence();
        __syncthreads();
    }

    uint32_t acc[2][4][2];
    #pragma unroll
    for (int mt = 0; mt < 2; mt++)
        #pragma unroll
        for (int nt = 0; nt < 4; nt++) { acc[mt][nt][0] = 0u; acc[mt][nt][1] = 0u; }

    const uint32_t a_lo = (uint32_t)((warpM * 32 + (lane & 15)) * ROWB + (lane >> 4) * 16);
    const uint32_t b_lo = (uint32_t)((warpN * 32 + (lane & 7) + ((lane >> 4) << 3)) * ROWB
                                     + (((lane >> 3) & 1) << 4));

    auto load_chunk = [&](int c, int st) {
        #pragma unroll
        for (int i = 0; i < 2; i++) {   // A: 128 rows x 8 = 1024 cp16
            int idx = i * 512 + tid;
            int r = idx >> 3, j = idx & 7;
            cp16(sb + A_OFF + (uint32_t)(st * A_STG + r * ROWB + j * 16),
                 g_embn + (size_t)(m0 + r) * DDIM + c * KC + j * 8);
        }
        #pragma unroll
        for (int i = 0; i < 2; i++) {   // B: 128 rows x 8 = 1024 cp16
            int idx = i * 512 + tid;
            int r = idx >> 3, j = idx & 7;
            int crow = col0 + r; if (crow >= NCLS) crow = NCLS - 1;
            cp16(sb + B_OFF + (uint32_t)(st * B_STG + r * ROWB + j * 16),
                 g_wn + (size_t)crow * DDIM + c * KC + j * 8);
        }
    };

    load_chunk(0, 0); cp_commit();
    load_chunk(1, 1); cp_commit();

    for (int c = 0; c < NCHUNK; c++) {
        const int st = c % NSTAGE;
        cp_wait1();
        __syncthreads();
        if (c + 2 < NCHUNK) load_chunk(c + 2, (c + 2) % NSTAGE);
        cp_commit();

        const uint32_t aB = sb + A_OFF + (uint32_t)st * A_STG + a_lo;
        const uint32_t bB = sb + B_OFF + (uint32_t)st * B_STG + b_lo;

        #pragma unroll
        for (int ks = 0; ks < 4; ks++) {
            uint32_t aF[2][4];
            #pragma unroll
            for (int mt = 0; mt < 2; mt++)
                ldm_x4(aF[mt], aB + ks * 32 + (uint32_t)mt * 16 * ROWB);
            uint32_t bF[2][4];
            #pragma unroll
            for (int p = 0; p < 2; p++)
                ldm_x4(bF[p], bB + ks * 32 + (uint32_t)p * 16 * ROWB);
            #pragma unroll
            for (int mt = 0; mt < 2; mt++)
                #pragma unroll
                for (int nt = 0; nt < 4; nt++)
                    mma_f16(acc[mt][nt], aF[mt], &bF[nt >> 1][(nt & 1) * 2]);
        }
    }
    __syncthreads();

    // ---- epilogue: exp row-sums + label gather ----
    float* sRowP = (float*)(smem + SR_OFF);

    #pragma unroll
    for (int mt = 0; mt < 2; mt++) {
        const int lrow0 = warpM * 32 + mt * 16 + g;
        const int grow0 = m0 + lrow0;
        const int grow1 = grow0 + 8;
        const int lab0 = (int)label[grow0 & 255];
        const int lab1 = (int)label[grow1 & 255];
        float sum0 = 0.f, sum1 = 0.f;
        #pragma unroll
        for (int nt = 0; nt < 4; nt++) {
            const float2 f0 = __half22float2(*reinterpret_cast<__half2*>(&acc[mt][nt][0]));
            const float2 f1 = __half22float2(*reinterpret_cast<__half2*>(&acc[mt][nt][1]));
            const int ccb = col0 + warpN * 32 + nt * 8 + tig * 2;
            if (ccb < NCLS) {
                sum0 += exp2f(f0.x * S_LOG2E);
                sum1 += exp2f(f1.x * S_LOG2E);
                if (ccb == lab0) g_coslab[grow0] = f0.x;
                if (ccb == lab1) g_coslab[grow1] = f1.x;
            }
            if (ccb + 1 < NCLS) {
                sum0 += exp2f(f0.y * S_LOG2E);
                sum1 += exp2f(f1.y * S_LOG2E);
                if (ccb + 1 == lab0) g_coslab[grow0] = f0.y;
                if (ccb + 1 == lab1) g_coslab[grow1] = f1.y;
            }
        }
        sum0 += __shfl_xor_sync(0xffffffffu, sum0, 1);
        sum0 += __shfl_xor_sync(0xffffffffu, sum0, 2);
        sum1 += __shfl_xor_sync(0xffffffffu, sum1, 1);
        sum1 += __shfl_xor_sync(0xffffffffu, sum1, 2);
        if (tig == 0) {
            sRowP[warpN * MT + lrow0]     = sum0;
            sRowP[warpN * MT + lrow0 + 8] = sum1;
        }
    }
    __syncthreads();
    if (tid < MT) {
        float s = sRowP[tid] + sRowP[MT + tid] + sRowP[2 * MT + tid] + sRowP[3 * MT + tid];
        g_part[(size_t)(m0 + tid) * NPART + tile] = s;
    }
}

// ============================================================
// Kernel C: fused per-row reduce + margin + mean
// ============================================================
__global__ void __launch_bounds__(256)
k_final(const long long* __restrict__ label, float* __restrict__ out) {
    int n = blockIdx.x;
    float s = 0.f;
    for (int t = threadIdx.x; t < NTILES; t += 256)
        s += g_part[(size_t)n * NPART + t];
    __shared__ float wsum[8];
    #pragma unroll
    for (int o = 16; o; o >>= 1) s += __shfl_xor_sync(0xffffffffu, s, o);
    if ((threadIdx.x & 31) == 0) wsum[threadIdx.x >> 5] = s;
    __syncthreads();
    __shared__ bool s_last;
    if (threadIdx.x == 0) {
        float tot = 0.f;
        #pragma unroll
        for (int w = 0; w < 8; w++) tot += wsum[w];
        float cosl = g_coslab[n];
        float sine = sqrtf(fminf(fmaxf(1.f - cosl * cosl, 0.f), 1.f));
        float phi = cosl * COS_M - sine * SIN_M;
        if (!(cosl > TH)) phi = cosl - MMRG;
        float total = tot - exp2f(cosl * S_LOG2E) + exp2f(phi * S_LOG2E);
        g_nll[n] = logf(total) - SCALE * phi;
        __threadfence();
        int ticket = atomicAdd(&g_ticket, 1);
        s_last = (ticket == TWO_B - 1);
    }
    __syncthreads();
    if (s_last && threadIdx.x < 32) {
        float v = 0.f;
        #pragma unroll
        for (int k = 0; k < TWO_B / 32; k++)
            v += g_nll[threadIdx.x + k * 32];
        #pragma unroll
        for (int o = 16; o; o >>= 1) v += __shfl_xor_sync(0xffffffffu, v, o);
        if (threadIdx.x == 0) out[0] = v / (float)TWO_B;
    }
}

// ============================================================
// launch — fork wprep onto a non-blocking side stream
// ============================================================
extern "C" void kernel_launch(void* const* d_in, const int* in_sizes, int n_in,
                              void* d_out, int out_size) {
    const float*     img  = (const float*)d_in[0];
    const float*     prof = (const float*)d_in[1];
    const float*     w    = (const float*)d_in[2];
    const long long* lab  = (const long long*)d_in[3];
    float* out = (float*)d_out;

    static cudaStream_t s2;
    static cudaEvent_t evFork, evJoin;
    static bool inited = false;
    if (!inited) {
        cudaStreamCreateWithFlags(&s2, cudaStreamNonBlocking);
        cudaEventCreateWithFlags(&evFork, cudaEventDisableTiming);
        cudaEventCreateWithFlags(&evJoin, cudaEventDisableTiming);
        cudaFuncSetAttribute(k_main, cudaFuncAttributeMaxDynamicSharedMemorySize, SMEM_BYTES);
        inited = true;
    }

    k_norm_emb<<<TWO_B, 256>>>(img, prof);     // also zeroes flags/ticket
    cudaEventRecord(evFork, 0);
    cudaStreamWaitEvent(s2, evFork, 0);
    k_wprep<<<NCONV, 256, 0, s2>>>(w);         // persistent, concurrent with k_main
    dim3 grid(4, NTILES);
    k_main<<<grid, 512, SMEM_BYTES>>>(w, lab);
    cudaEventRecord(evJoin, s2);
    cudaStreamWaitEvent(0, evJoin, 0);
    k_final<<<TWO_B, 256>>>(lab, out);
}

// round 17
// speedup vs baseline: 1.2392x; 1.2392x over previous
#include <cuda_runtime.h>
#include <cuda_fp16.h>
#include <math.h>
#include <stdint.h>

// ---------------- problem constants ----------------
#define TWO_B 512
#define BHALF 256
#define DDIM  512
#define NCLS  100000
#define SCALE 30.0f
#define S_LOG2E 43.280851226668914f  // 30 * log2(e)
#define COS_M 0.8775825618903728f
#define SIN_M 0.4794255386042030f
#define TH   (-0.8775825618903728f)
#define MMRG  0.2397127693021015f

// ---------------- GEMM tiling ----------------
#define MT      128                   // rows per CTA
#define NT      128                   // classes per CTA
#define NTILES  782                   // ceil(NCLS/NT)
#define NPART   784
#define KC      64                    // K fp16 elems per chunk (128 B/row)
#define NCHUNK  8
#define NSTAGE  3
#define ROWB    144                   // padded bytes per smem row (conflict-free)

// fused prep grid: 512 emb rows + 100000 weight rows, 8 rows/block
#define PREP_ROWS (TWO_B + NCLS)
#define PREP_BLOCKS ((PREP_ROWS + 7) / 8)

// smem layout (bytes)
#define A_OFF   0
#define A_STG   (MT * ROWB)                    // 18432, 3 stages
#define B_OFF   (NSTAGE * A_STG)               // 55296
#define B_STG   (NT * ROWB)                    // 18432
#define SR_OFF  (B_OFF + NSTAGE * B_STG)       // 110592 : sRowP[4][128] floats
#define SMEM_BYTES (SR_OFF + 4 * MT * 4)       // 112640 -> 2 CTAs/SM

// ---------------- device scratch ----------------
__device__ __align__(16) uint16_t g_embn[TWO_B * DDIM];      // normalized emb, fp16
__device__ __align__(16) uint16_t g_wn[(size_t)NCLS * DDIM]; // normalized weight, fp16
__device__ float g_part[TWO_B * NPART];
__device__ float g_coslab[TWO_B];
__device__ float g_nll[TWO_B];
__device__ int   g_ticket;                                   // last-block election

// ---------------- helpers ----------------
__device__ __forceinline__ uint32_t smem_u32(const void* p) {
    uint32_t a;
    asm("{ .reg .u64 t; cvta.to.shared.u64 t, %1; cvt.u32.u64 %0, t; }" : "=r"(a) : "l"(p));
    return a;
}
__device__ __forceinline__ void cp16(uint32_t dst, const void* src) {
    asm volatile("cp.async.cg.shared.global [%0], [%1], 16;" :: "r"(dst), "l"(src));
}
__device__ __forceinline__ void cp_commit() { asm volatile("cp.async.commit_group;"); }
__device__ __forceinline__ void cp_wait1()  { asm volatile("cp.async.wait_group 1;"); }

__device__ __forceinline__ uint32_t pack_f16x2(float lo, float hi) {
    uint32_t r;
    asm("cvt.rn.f16x2.f32 %0, %1, %2;" : "=r"(r) : "f"(hi), "f"(lo));
    return r;
}
__device__ __forceinline__ void ldm_x4(uint32_t* r, uint32_t addr) {
    asm volatile("ldmatrix.sync.aligned.m8n8.x4.shared.b16 {%0,%1,%2,%3}, [%4];"
                 : "=r"(r[0]), "=r"(r[1]), "=r"(r[2]), "=r"(r[3]) : "r"(addr));
}
// fp16 inputs, fp16 accumulators (packed half2 in 2 regs)
__device__ __forceinline__ void mma_f16(uint32_t* d, const uint32_t* a, const uint32_t* b) {
    asm volatile(
        "mma.sync.aligned.m16n8k16.row.col.f16.f16.f16.f16 "
        "{%0,%1}, {%2,%3,%4,%5}, {%6,%7}, {%0,%1};"
        : "+r"(d[0]), "+r"(d[1])
        : "r"(a[0]), "r"(a[1]), "r"(a[2]), "r"(a[3]), "r"(b[0]), "r"(b[1]));
}

// ============================================================
// Kernel P: fused prep — normalize emb rows AND weight rows
//   to fp16, one warp per row. rows 0..511 = emb, 512.. = weight.
// ============================================================
__global__ void __launch_bounds__(256)
k_prep(const float* __restrict__ img, const float* __restrict__ prof,
       const float* __restrict__ weight) {
    if (blockIdx.x == 0 && threadIdx.x == 0) g_ticket = 0;
    const int row  = blockIdx.x * 8 + (threadIdx.x >> 5);
    const int lane = threadIdx.x & 31;
    if (row >= PREP_ROWS) return;

    const float* src;
    uint16_t* dst16;
    if (row < TWO_B) {
        src = (row < BHALF) ? (img + (size_t)row * DDIM)
                            : (prof + (size_t)(row - BHALF) * DDIM);
        dst16 = g_embn + (size_t)row * DDIM;
    } else {
        const int wr = row - TWO_B;
        src = weight + (size_t)wr * DDIM;
        dst16 = g_wn + (size_t)wr * DDIM;
    }

    const float4* s4 = (const float4*)src;
    float4 v[4];
    float ss = 0.f;
    #pragma unroll
    for (int t = 0; t < 4; t++) {
        v[t] = s4[lane * 4 + t];                 // lane owns floats 16*lane..+15
        ss = fmaf(v[t].x, v[t].x, fmaf(v[t].y, v[t].y,
             fmaf(v[t].z, v[t].z, fmaf(v[t].w, v[t].w, ss))));
    }
    #pragma unroll
    for (int o = 16; o; o >>= 1) ss += __shfl_xor_sync(0xffffffffu, ss, o);
    const float rinv = rsqrtf(ss);
    uint4 out[2];
    uint32_t* ou = (uint32_t*)out;
    #pragma unroll
    for (int t = 0; t < 4; t++) {
        ou[t * 2 + 0] = pack_f16x2(v[t].x * rinv, v[t].y * rinv);
        ou[t * 2 + 1] = pack_f16x2(v[t].z * rinv, v[t].w * rinv);
    }
    uint4* d4 = (uint4*)dst16;
    d4[lane * 2 + 0] = out[0];
    d4[lane * 2 + 1] = out[1];
}

// ============================================================
// Kernel B: fp16 mma.sync GEMM (fp16 accum) + exp epilogue
//   CTA 128x128, 512 threads (warps 4M x 4N, warp tile 32x32),
//   2 CTAs/SM (8 warps/SMSP). KC=64, 8 chunks, 3 stages.
// ============================================================
__global__ void __launch_bounds__(512, 2)
k_main(const long long* __restrict__ label) {
    extern __shared__ char smem[];
    const uint32_t sb = smem_u32(smem);
    const int tid   = threadIdx.x;
    const int lane  = tid & 31;
    const int wrp   = tid >> 5;
    const int warpM = wrp & 3;     // 0..3 (32 rows each)
    const int warpN = wrp >> 2;    // 0..3 (32 cols each)
    const int g     = lane >> 2;
    const int tig   = lane & 3;

    const int m0   = blockIdx.x * MT;
    const int col0 = blockIdx.y * NT;

    uint32_t acc[2][4][2];         // packed f16x2 accumulators
    #pragma unroll
    for (int mt = 0; mt < 2; mt++)
        #pragma unroll
        for (int nt = 0; nt < 4; nt++) {
            acc[mt][nt][0] = 0u;
            acc[mt][nt][1] = 0u;
        }

    // per-lane ldmatrix offsets (bytes, within a stage)
    const uint32_t a_lo = (uint32_t)((warpM * 32 + (lane & 15)) * ROWB + (lane >> 4) * 16);
    const uint32_t b_lo = (uint32_t)((warpN * 32 + (lane & 7) + ((lane >> 4) << 3)) * ROWB
                                     + (((lane >> 3) & 1) << 4));

    // ---- chunk loader (rows of 128B = 8 x cp16), 512 threads ----
    auto load_chunk = [&](int c, int st) {
        #pragma unroll
        for (int i = 0; i < 2; i++) {   // A: 128 rows x 8 = 1024 cp16
            int idx = i * 512 + tid;
            int r = idx >> 3, j = idx & 7;
            cp16(sb + A_OFF + (uint32_t)(st * A_STG + r * ROWB + j * 16),
                 g_embn + (size_t)(m0 + r) * DDIM + c * KC + j * 8);
        }
        #pragma unroll
        for (int i = 0; i < 2; i++) {   // B: 128 rows x 8 = 1024 cp16
            int idx = i * 512 + tid;
            int r = idx >> 3, j = idx & 7;
            int crow = col0 + r; if (crow >= NCLS) crow = NCLS - 1;
            cp16(sb + B_OFF + (uint32_t)(st * B_STG + r * ROWB + j * 16),
                 g_wn + (size_t)crow * DDIM + c * KC + j * 8);
        }
    };

    load_chunk(0, 0); cp_commit();
    load_chunk(1, 1); cp_commit();

    for (int c = 0; c < NCHUNK; c++) {
        const int st = c % NSTAGE;
        cp_wait1();
        __syncthreads();
        if (c + 2 < NCHUNK) load_chunk(c + 2, (c + 2) % NSTAGE);
        cp_commit();

        const uint32_t aB = sb + A_OFF + (uint32_t)st * A_STG + a_lo;
        const uint32_t bB = sb + B_OFF + (uint32_t)st * B_STG + b_lo;

        #pragma unroll
        for (int ks = 0; ks < 4; ks++) {
            uint32_t aF[2][4];
            #pragma unroll
            for (int mt = 0; mt < 2; mt++)
                ldm_x4(aF[mt], aB + ks * 32 + (uint32_t)mt * 16 * ROWB);
            uint32_t bF[2][4];
            #pragma unroll
            for (int p = 0; p < 2; p++)
                ldm_x4(bF[p], bB + ks * 32 + (uint32_t)p * 16 * ROWB);
            #pragma unroll
            for (int mt = 0; mt < 2; mt++)
                #pragma unroll
                for (int nt = 0; nt < 4; nt++)
                    mma_f16(acc[mt][nt], aF[mt], &bF[nt >> 1][(nt & 1) * 2]);
        }
    }
    __syncthreads();

    // ---- epilogue: exp row-sums + label gather ----
    float* sRowP = (float*)(smem + SR_OFF);

    #pragma unroll
    for (int mt = 0; mt < 2; mt++) {
        const int lrow0 = warpM * 32 + mt * 16 + g;
        const int grow0 = m0 + lrow0;
        const int grow1 = grow0 + 8;
        const int lab0 = (int)label[grow0 & 255];
        const int lab1 = (int)label[grow1 & 255];
        float sum0 = 0.f, sum1 = 0.f;
        #pragma unroll
        for (int nt = 0; nt < 4; nt++) {
            const float2 f0 = __half22float2(*reinterpret_cast<__half2*>(&acc[mt][nt][0]));
            const float2 f1 = __half22float2(*reinterpret_cast<__half2*>(&acc[mt][nt][1]));
            const int ccb = col0 + warpN * 32 + nt * 8 + tig * 2;
            if (ccb < NCLS) {
                sum0 += exp2f(f0.x * S_LOG2E);
                sum1 += exp2f(f1.x * S_LOG2E);
                if (ccb == lab0) g_coslab[grow0] = f0.x;
                if (ccb == lab1) g_coslab[grow1] = f1.x;
            }
            if (ccb + 1 < NCLS) {
                sum0 += exp2f(f0.y * S_LOG2E);
                sum1 += exp2f(f1.y * S_LOG2E);
                if (ccb + 1 == lab0) g_coslab[grow0] = f0.y;
                if (ccb + 1 == lab1) g_coslab[grow1] = f1.y;
            }
        }
        sum0 += __shfl_xor_sync(0xffffffffu, sum0, 1);
        sum0 += __shfl_xor_sync(0xffffffffu, sum0, 2);
        sum1 += __shfl_xor_sync(0xffffffffu, sum1, 1);
        sum1 += __shfl_xor_sync(0xffffffffu, sum1, 2);
        if (tig == 0) {
            sRowP[warpN * MT + lrow0]     = sum0;
            sRowP[warpN * MT + lrow0 + 8] = sum1;
        }
    }
    __syncthreads();
    if (tid < MT) {
        float s = sRowP[tid] + sRowP[MT + tid] + sRowP[2 * MT + tid] + sRowP[3 * MT + tid];
        g_part[(size_t)(m0 + tid) * NPART + blockIdx.y] = s;
    }
}

// ============================================================
// Kernel C: fused per-row reduce + margin + mean
//   512 blocks x 256 threads; last block (atomic ticket) does
//   the deterministic fixed-order mean.
// ============================================================
__global__ void __launch_bounds__(256)
k_final(const long long* __restrict__ label, float* __restrict__ out) {
    int n = blockIdx.x;
    float s = 0.f;
    for (int t = threadIdx.x; t < NTILES; t += 256)
        s += g_part[(size_t)n * NPART + t];
    __shared__ float wsum[8];
    #pragma unroll
    for (int o = 16; o; o >>= 1) s += __shfl_xor_sync(0xffffffffu, s, o);
    if ((threadIdx.x & 31) == 0) wsum[threadIdx.x >> 5] = s;
    __syncthreads();
    __shared__ bool s_last;
    if (threadIdx.x == 0) {
        float tot = 0.f;
        #pragma unroll
        for (int w = 0; w < 8; w++) tot += wsum[w];
        float cosl = g_coslab[n];
        float sine = sqrtf(fminf(fmaxf(1.f - cosl * cosl, 0.f), 1.f));
        float phi = cosl * COS_M - sine * SIN_M;
        if (!(cosl > TH)) phi = cosl - MMRG;
        float total = tot - exp2f(cosl * S_LOG2E) + exp2f(phi * S_LOG2E);
        g_nll[n] = logf(total) - SCALE * phi;
        __threadfence();
        int ticket = atomicAdd(&g_ticket, 1);
        s_last = (ticket == TWO_B - 1);
    }
    __syncthreads();
    if (s_last && threadIdx.x < 32) {
        // deterministic fixed-order mean: thread t sums rows t, t+32, ...
        float v = 0.f;
        #pragma unroll
        for (int k = 0; k < TWO_B / 32; k++)
            v += g_nll[threadIdx.x + k * 32];
        #pragma unroll
        for (int o = 16; o; o >>= 1) v += __shfl_xor_sync(0xffffffffu, v, o);
        if (threadIdx.x == 0) out[0] = v / (float)TWO_B;
    }
}

// ============================================================
// launch
// ============================================================
extern "C" void kernel_launch(void* const* d_in, const int* in_sizes, int n_in,
                              void* d_out, int out_size) {
    const float*     img  = (const float*)d_in[0];
    const float*     prof = (const float*)d_in[1];
    const float*     w    = (const float*)d_in[2];
    const long long* lab  = (const long long*)d_in[3];
    float* out = (float*)d_out;

    cudaFuncSetAttribute(k_main, cudaFuncAttributeMaxDynamicSharedMemorySize, SMEM_BYTES);

    k_prep<<<PREP_BLOCKS, 256>>>(img, prof, w);   // emb + weight norm, fp16; ticket reset
    dim3 grid(4, NTILES);                         // x fastest -> 4-way B-tile L2 reuse
    k_main<<<grid, 512, SMEM_BYTES>>>(lab);
    k_final<<<TWO_B, 256>>>(lab, out);
}